// round 1
// baseline (speedup 1.0000x reference)
#include <cuda_runtime.h>
#include <cuda_bf16.h>

#define RADIUS   64
#define PAD_VAL  -1000.0f
#define ROW      4096
#define NROWS    1024
#define CHUNK    16
#define NCHUNK   256          // chunks per row = ROW/CHUNK
#define THREADS  256

// One block per row. Thread c owns chunk c (16 consecutive floats).
// Window max over h[i+1..i+64] decomposed into per-chunk prefix/suffix maxes
// of ghat[q] = h[..+q] - q (local offset -> small magnitudes, fp32-safe).
__global__ __launch_bounds__(THREADS) void h2i_kernel(
    const float* __restrict__ hf, float* __restrict__ out)
{
    const int row = blockIdx.x;
    const int c   = threadIdx.x;                 // chunk id within row
    const float* rp = hf  + (size_t)row * ROW;
    float*       op = out + (size_t)row * ROW;

    // +4 virtual pad chunks covering indices [4096, 4160); stride 17 kills bank conflicts
    __shared__ float s_pre[NCHUNK + 4][17];
    __shared__ float s_M  [NCHUNK + 4];

    // ---- load 16 floats (4x float4) ----
    float x[16];
    const float4* p4 = (const float4*)(rp + c * CHUNK);
    #pragma unroll
    for (int v = 0; v < 4; v++) {
        float4 t = p4[v];
        x[4*v+0] = t.x; x[4*v+1] = t.y; x[4*v+2] = t.z; x[4*v+3] = t.w;
    }

    // ---- ghat[q] = x[q] - q  (local slope offset) ----
    float g[16];
    #pragma unroll
    for (int q = 0; q < 16; q++) g[q] = x[q] - (float)q;

    // ---- prefix maxes -> shared; chunk max M = pre[15] ----
    {
        float pre = g[0];
        s_pre[c][0] = pre;
        #pragma unroll
        for (int q = 1; q < 16; q++) { pre = fmaxf(pre, g[q]); s_pre[c][q] = pre; }
        s_M[c] = pre;
    }

    // ---- suffix maxes (registers): suf[p] = max g[p..15], suf[16] = -inf ----
    float suf[17];
    suf[16] = -3.0e38f;
    suf[15] = g[15];
    #pragma unroll
    for (int q = 14; q >= 0; q--) suf[q] = fmaxf(g[q], suf[q + 1]);

    // ---- pad chunks: h = PAD_VAL everywhere => ghat[q] = PAD-q, prefix max = PAD, M = PAD ----
    if (c < 4) {
        s_M[NCHUNK + c] = PAD_VAL;
        #pragma unroll
        for (int q = 0; q < 16; q++) s_pre[NCHUNK + c][q] = PAD_VAL;
    }
    __syncthreads();

    // ---- middle: chunks c+1..c+3 fully inside every window of this chunk ----
    const float mid = fmaxf(fmaxf(s_M[c + 1] - 16.0f,
                                  s_M[c + 2] - 32.0f),
                                  s_M[c + 3] - 48.0f);

    // ---- combine per element: wmax = p + max(suf(p+1), mid, pre_{c+4}(p) - 64) ----
    float r[16];
    #pragma unroll
    for (int p = 0; p < 16; p++) {
        float w = fmaxf(suf[p + 1], mid);
        w = fmaxf(w, s_pre[c + 4][p] - 64.0f);
        float v = (float)p + w - x[p];
        r[p] = fmaxf(v, 0.0f);
    }

    // ---- store (4x float4) ----
    float4* o4 = (float4*)(op + c * CHUNK);
    #pragma unroll
    for (int v = 0; v < 4; v++)
        o4[v] = make_float4(r[4*v+0], r[4*v+1], r[4*v+2], r[4*v+3]);
}

extern "C" void kernel_launch(void* const* d_in, const int* in_sizes, int n_in,
                              void* d_out, int out_size)
{
    const float* hf = (const float*)d_in[0];
    float* out = (float*)d_out;
    (void)in_sizes; (void)n_in; (void)out_size;
    h2i_kernel<<<NROWS, THREADS>>>(hf, out);
}